// round 1
// baseline (speedup 1.0000x reference)
#include <cuda_runtime.h>
#include <math.h>

#define B_  2
#define S_  2048
#define D_  1024
#define H_  16
#define HD_ 64

// ---------------- scratch (no cudaMalloc allowed) ----------------
__device__ float g_Q[(size_t)B_ * S_ * D_];
__device__ float g_K[(size_t)B_ * S_ * D_];
__device__ float g_V[(size_t)B_ * S_ * D_];
__device__ float g_ctx[(size_t)B_ * S_ * D_];
__device__ float g_scores[(size_t)B_ * H_ * S_ * S_];   // 536 MB

// ======================================================================
// GEMM  C = alpha * A * B^T (+bias), A[M,K] row-major, B[N,K] row-major.
// Tiles: 128x128x8, 256 threads, 8x8 per thread.
// Batched over blockIdx.z via (z/zdiv, z%zdiv) two-stride offsets.
// ======================================================================
__global__ void __launch_bounds__(256)
gemm_nt128(const float* __restrict__ A, int lda,
           const float* __restrict__ B, int ldb,
           float* __restrict__ C, int ldc,
           int K, float alpha, const float* __restrict__ bias,
           int zdiv,
           size_t sA1, size_t sA2,
           size_t sB1, size_t sB2,
           size_t sC1, size_t sC2)
{
    int z = blockIdx.z;
    int z1 = z / zdiv, z2 = z % zdiv;
    A += z1 * sA1 + z2 * sA2;
    B += z1 * sB1 + z2 * sB2;
    C += z1 * sC1 + z2 * sC2;

    __shared__ float As[8][128];
    __shared__ float Bs[8][128];

    const int bm = blockIdx.y * 128;
    const int bn = blockIdx.x * 128;
    const int tid = threadIdx.x;
    const int tx = tid % 16;          // col group
    const int ty = tid / 16;          // row group

    const int lrow = tid / 2;          // 0..127
    const int lcol = (tid % 2) * 4;    // 0 or 4

    float acc[8][8];
#pragma unroll
    for (int i = 0; i < 8; i++)
#pragma unroll
        for (int j = 0; j < 8; j++) acc[i][j] = 0.f;

    for (int k0 = 0; k0 < K; k0 += 8) {
        float4 a = *(const float4*)(A + (size_t)(bm + lrow) * lda + k0 + lcol);
        float4 b = *(const float4*)(B + (size_t)(bn + lrow) * ldb + k0 + lcol);
        As[lcol + 0][lrow] = a.x; As[lcol + 1][lrow] = a.y;
        As[lcol + 2][lrow] = a.z; As[lcol + 3][lrow] = a.w;
        Bs[lcol + 0][lrow] = b.x; Bs[lcol + 1][lrow] = b.y;
        Bs[lcol + 2][lrow] = b.z; Bs[lcol + 3][lrow] = b.w;
        __syncthreads();

#pragma unroll
        for (int k = 0; k < 8; k++) {
            float ra[8], rb[8];
#pragma unroll
            for (int i = 0; i < 8; i++) ra[i] = As[k][ty * 8 + i];
#pragma unroll
            for (int j = 0; j < 8; j++) rb[j] = Bs[k][tx * 8 + j];
#pragma unroll
            for (int i = 0; i < 8; i++)
#pragma unroll
                for (int j = 0; j < 8; j++) acc[i][j] += ra[i] * rb[j];
        }
        __syncthreads();
    }

#pragma unroll
    for (int i = 0; i < 8; i++) {
        int row = bm + ty * 8 + i;
#pragma unroll
        for (int j = 0; j < 8; j++) {
            int col = bn + tx * 8 + j;
            float bv = bias ? bias[col] : 0.f;
            C[(size_t)row * ldc + col] = alpha * acc[i][j] + bv;
        }
    }
}

// ======================================================================
// GEMM  C = A * B, A[M,K] row-major, B[K,N] row-major.
// Tiles: 64x64x16, 256 threads, 4x4 per thread. (used for attn @ V)
// ======================================================================
__global__ void __launch_bounds__(256)
gemm_nn64(const float* __restrict__ A, int lda,
          const float* __restrict__ B, int ldb,
          float* __restrict__ C, int ldc,
          int K, int zdiv,
          size_t sA1, size_t sA2,
          size_t sB1, size_t sB2,
          size_t sC1, size_t sC2)
{
    int z = blockIdx.z;
    int z1 = z / zdiv, z2 = z % zdiv;
    A += z1 * sA1 + z2 * sA2;
    B += z1 * sB1 + z2 * sB2;
    C += z1 * sC1 + z2 * sC2;

    __shared__ float As[16][64];
    __shared__ float Bs[16][64];

    const int bm = blockIdx.y * 64;
    const int bn = blockIdx.x * 64;
    const int tid = threadIdx.x;
    const int tx = tid % 16;
    const int ty = tid / 16;

    // A tile load mapping: 64 rows x 16 k
    const int arow = tid / 4;            // 0..63
    const int akc  = (tid % 4) * 4;      // 0,4,8,12
    // B tile load mapping: 16 k x 64 n
    const int brow = tid / 16;           // 0..15
    const int bc   = (tid % 16) * 4;     // 0..60

    float acc[4][4];
#pragma unroll
    for (int i = 0; i < 4; i++)
#pragma unroll
        for (int j = 0; j < 4; j++) acc[i][j] = 0.f;

    for (int k0 = 0; k0 < K; k0 += 16) {
        float4 a = *(const float4*)(A + (size_t)(bm + arow) * lda + k0 + akc);
        As[akc + 0][arow] = a.x; As[akc + 1][arow] = a.y;
        As[akc + 2][arow] = a.z; As[akc + 3][arow] = a.w;
        float4 b = *(const float4*)(B + (size_t)(k0 + brow) * ldb + bn + bc);
        *(float4*)&Bs[brow][bc] = b;
        __syncthreads();

#pragma unroll
        for (int k = 0; k < 16; k++) {
            float ra[4], rb[4];
#pragma unroll
            for (int i = 0; i < 4; i++) ra[i] = As[k][ty * 4 + i];
#pragma unroll
            for (int j = 0; j < 4; j++) rb[j] = Bs[k][tx * 4 + j];
#pragma unroll
            for (int i = 0; i < 4; i++)
#pragma unroll
                for (int j = 0; j < 4; j++) acc[i][j] += ra[i] * rb[j];
        }
        __syncthreads();
    }

#pragma unroll
    for (int i = 0; i < 4; i++) {
        int row = bm + ty * 4 + i;
#pragma unroll
        for (int j = 0; j < 4; j++) {
            int col = bn + tx * 4 + j;
            C[(size_t)row * ldc + col] = acc[i][j];
        }
    }
}

// ======================================================================
// Row softmax in-place. One block (256 thr) per row of 2048.
// ======================================================================
__device__ __forceinline__ float warp_max(float v) {
#pragma unroll
    for (int o = 16; o; o >>= 1) v = fmaxf(v, __shfl_xor_sync(0xffffffffu, v, o));
    return v;
}
__device__ __forceinline__ float warp_sum(float v) {
#pragma unroll
    for (int o = 16; o; o >>= 1) v += __shfl_xor_sync(0xffffffffu, v, o);
    return v;
}

__global__ void __launch_bounds__(256)
softmax_rows(float* __restrict__ scores)
{
    size_t row = blockIdx.x;
    float* p = scores + row * (size_t)S_;
    const int t = threadIdx.x;

    float v[8];
    float mx = -INFINITY;
#pragma unroll
    for (int i = 0; i < 8; i++) {
        v[i] = p[t + i * 256];
        mx = fmaxf(mx, v[i]);
    }

    __shared__ float red[8];
    float wm = warp_max(mx);
    if ((t & 31) == 0) red[t >> 5] = wm;
    __syncthreads();
    if (t < 32) {
        float x = (t < 8) ? red[t] : -INFINITY;
        x = warp_max(x);
        if (t == 0) red[0] = x;
    }
    __syncthreads();
    mx = red[0];

    float s = 0.f;
#pragma unroll
    for (int i = 0; i < 8; i++) {
        v[i] = __expf(v[i] - mx);
        s += v[i];
    }
    __syncthreads();
    float ws = warp_sum(s);
    if ((t & 31) == 0) red[t >> 5] = ws;
    __syncthreads();
    if (t < 32) {
        float x = (t < 8) ? red[t] : 0.f;
        x = warp_sum(x);
        if (t == 0) red[0] = x;
    }
    __syncthreads();
    float inv = 1.0f / red[0];

#pragma unroll
    for (int i = 0; i < 8; i++) p[t + i * 256] = v[i] * inv;
}

// ======================================================================
// avg_attn[b,q,k] = mean_h attn[b,h,q,k]
// ======================================================================
__global__ void __launch_bounds__(256)
avg_heads(const float* __restrict__ scores, float* __restrict__ out)
{
    size_t idx = (size_t)blockIdx.x * 256 + threadIdx.x;   // < B*S*S
    size_t b = idx / ((size_t)S_ * S_);
    size_t rem = idx % ((size_t)S_ * S_);
    float s = 0.f;
#pragma unroll
    for (int h = 0; h < H_; h++)
        s += scores[((b * H_ + h) * (size_t)S_ * S_) + rem];
    out[idx] = s * (1.0f / H_);
}

// ======================================================================
extern "C" void kernel_launch(void* const* d_in, const int* in_sizes, int n_in,
                              void* d_out, int out_size)
{
    const float* query = (const float*)d_in[0];
    const float* Wq = (const float*)d_in[1];
    const float* bq = (const float*)d_in[2];
    const float* Wk = (const float*)d_in[3];
    const float* bk = (const float*)d_in[4];
    const float* Wv = (const float*)d_in[5];
    const float* bv = (const float*)d_in[6];
    const float* Wo = (const float*)d_in[7];
    const float* bo = (const float*)d_in[8];
    float* out = (float*)d_out;

    float *Q, *K, *V, *CTX, *SC;
    cudaGetSymbolAddress((void**)&Q,   g_Q);
    cudaGetSymbolAddress((void**)&K,   g_K);
    cudaGetSymbolAddress((void**)&V,   g_V);
    cudaGetSymbolAddress((void**)&CTX, g_ctx);
    cudaGetSymbolAddress((void**)&SC,  g_scores);

    const int M = B_ * S_;   // 4096
    const float iscale = 1.0f / 8.0f;   // 1/sqrt(HD)

    // ---- Q/K/V projections: [4096,1024] @ W^T + b ----
    dim3 gproj(D_ / 128, M / 128, 1);
    gemm_nt128<<<gproj, 256>>>(query, D_, Wq, D_, Q, D_, D_, 1.f, bq,
                               1, 0, 0, 0, 0, 0, 0);
    gemm_nt128<<<gproj, 256>>>(query, D_, Wk, D_, K, D_, D_, 1.f, bk,
                               1, 0, 0, 0, 0, 0, 0);
    gemm_nt128<<<gproj, 256>>>(query, D_, Wv, D_, V, D_, D_, 1.f, bv,
                               1, 0, 0, 0, 0, 0, 0);

    // ---- scores[b,h] = Q_h @ K_h^T * 1/8 : batched over z = b*H+h ----
    dim3 gsc(S_ / 128, S_ / 128, B_ * H_);
    gemm_nt128<<<gsc, 256>>>(Q, D_, K, D_, SC, S_, HD_, iscale, nullptr,
                             H_,
                             (size_t)S_ * D_, HD_,
                             (size_t)S_ * D_, HD_,
                             (size_t)H_ * S_ * S_, (size_t)S_ * S_);

    // ---- softmax over each of B*H*S rows ----
    softmax_rows<<<B_ * H_ * S_, 256>>>(SC);

    // ---- avg over heads -> second output chunk ----
    avg_heads<<<(B_ * (size_t)S_ * S_) / 256, 256>>>(SC, out + (size_t)M * D_);

    // ---- ctx[b,h] = attn @ V_h : batched ----
    dim3 gcx(HD_ / 64, S_ / 64, B_ * H_);
    gemm_nn64<<<gcx, 256>>>(SC, S_, V, D_, CTX, D_, S_,
                            H_,
                            (size_t)H_ * S_ * S_, (size_t)S_ * S_,
                            (size_t)S_ * D_, HD_,
                            (size_t)S_ * D_, HD_);

    // ---- output projection ----
    gemm_nt128<<<gproj, 256>>>(CTX, D_, Wo, D_, out, D_, D_, 1.f, bo,
                               1, 0, 0, 0, 0, 0, 0);
}

// round 3
// speedup vs baseline: 3.5232x; 3.5232x over previous
#include <cuda_runtime.h>
#include <cuda_bf16.h>
#include <math.h>
#include <stdint.h>

#define B_  2
#define S_  2048
#define D_  1024
#define H_  16
#define HD_ 64

// ---------------- scratch (no cudaMalloc allowed) ----------------
__device__ float g_Q[(size_t)B_ * S_ * D_];
__device__ float g_K[(size_t)B_ * S_ * D_];
__device__ float g_V[(size_t)B_ * S_ * D_];
__device__ float g_ctx[(size_t)B_ * S_ * D_];
__device__ float g_scores[(size_t)B_ * H_ * S_ * S_];   // 536 MB

// ======================= PTX helpers =======================
__device__ __forceinline__ uint32_t sptr(const void* p) {
    return (uint32_t)__cvta_generic_to_shared(p);
}
__device__ __forceinline__ void ldm_x4(uint32_t (&r)[4], uint32_t addr) {
    asm volatile("ldmatrix.sync.aligned.m8n8.x4.shared.b16 {%0,%1,%2,%3}, [%4];"
                 : "=r"(r[0]), "=r"(r[1]), "=r"(r[2]), "=r"(r[3]) : "r"(addr));
}
__device__ __forceinline__ void ldm_x2(uint32_t (&r)[2], uint32_t addr) {
    asm volatile("ldmatrix.sync.aligned.m8n8.x2.shared.b16 {%0,%1}, [%2];"
                 : "=r"(r[0]), "=r"(r[1]) : "r"(addr));
}
__device__ __forceinline__ void ldm_x2t(uint32_t (&r)[2], uint32_t addr) {
    asm volatile("ldmatrix.sync.aligned.m8n8.x2.trans.shared.b16 {%0,%1}, [%2];"
                 : "=r"(r[0]), "=r"(r[1]) : "r"(addr));
}
__device__ __forceinline__ void mma_bf16(float (&c)[4], const uint32_t (&a)[4],
                                         const uint32_t (&b)[2]) {
    asm volatile(
        "mma.sync.aligned.m16n8k16.row.col.f32.bf16.bf16.f32 "
        "{%0,%1,%2,%3}, {%4,%5,%6,%7}, {%8,%9}, {%0,%1,%2,%3};"
        : "+f"(c[0]), "+f"(c[1]), "+f"(c[2]), "+f"(c[3])
        : "r"(a[0]), "r"(a[1]), "r"(a[2]), "r"(a[3]), "r"(b[0]), "r"(b[1]));
}
__device__ __forceinline__ void split_bf16(float x, __nv_bfloat16& hi, __nv_bfloat16& lo) {
    hi = __float2bfloat16(x);
    lo = __float2bfloat16(x - __bfloat162float(hi));
}

// ======================================================================
// Tensor-core GEMM  C = alpha * A * B^T (+bias)
// A[M,K] rm, B[N,K] rm. Tiles 128x128x32, 256 thr (8 warps, 2x4, 64x32 each).
// bf16x3: D += Ah*Bh + Ah*Bl + Al*Bh  (fp32 accum)
// ======================================================================
__global__ void __launch_bounds__(256)
gemm_nt_tc(const float* __restrict__ A, int lda,
           const float* __restrict__ B, int ldb,
           float* __restrict__ C, int ldc,
           int K, float alpha, const float* __restrict__ bias,
           int zdiv,
           size_t sA1, size_t sA2,
           size_t sB1, size_t sB2,
           size_t sC1, size_t sC2)
{
    int z = blockIdx.z;
    int z1 = z / zdiv, z2 = z % zdiv;
    A += z1 * sA1 + z2 * sA2;
    B += z1 * sB1 + z2 * sB2;
    C += z1 * sC1 + z2 * sC2;

    __shared__ __nv_bfloat16 Ah[128][40], Al[128][40];
    __shared__ __nv_bfloat16 Bh[128][40], Bl[128][40];

    const int bm = blockIdx.y * 128;
    const int bn = blockIdx.x * 128;
    const int tid = threadIdx.x;
    const int warp = tid >> 5, lane = tid & 31;
    const int wm = warp >> 2, wn = warp & 3;          // 2 x 4 warps

    float acc[4][4][4];
#pragma unroll
    for (int i = 0; i < 4; i++)
#pragma unroll
        for (int j = 0; j < 4; j++)
#pragma unroll
            for (int l = 0; l < 4; l++) acc[i][j][l] = 0.f;

    for (int k0 = 0; k0 < K; k0 += 32) {
        // ---- load + split 128x32 tiles of A and B ----
#pragma unroll
        for (int i = 0; i < 4; i++) {
            int f = tid + i * 256;
            int row = f >> 3, c = (f & 7) * 4;
            float4 a = *(const float4*)(A + (size_t)(bm + row) * lda + k0 + c);
            a.x *= alpha; a.y *= alpha; a.z *= alpha; a.w *= alpha;
            __nv_bfloat16 h0, l0, h1, l1, h2, l2, h3, l3;
            split_bf16(a.x, h0, l0); split_bf16(a.y, h1, l1);
            split_bf16(a.z, h2, l2); split_bf16(a.w, h3, l3);
            Ah[row][c] = h0; Ah[row][c+1] = h1; Ah[row][c+2] = h2; Ah[row][c+3] = h3;
            Al[row][c] = l0; Al[row][c+1] = l1; Al[row][c+2] = l2; Al[row][c+3] = l3;

            float4 b = *(const float4*)(B + (size_t)(bn + row) * ldb + k0 + c);
            split_bf16(b.x, h0, l0); split_bf16(b.y, h1, l1);
            split_bf16(b.z, h2, l2); split_bf16(b.w, h3, l3);
            Bh[row][c] = h0; Bh[row][c+1] = h1; Bh[row][c+2] = h2; Bh[row][c+3] = h3;
            Bl[row][c] = l0; Bl[row][c+1] = l1; Bl[row][c+2] = l2; Bl[row][c+3] = l3;
        }
        __syncthreads();

#pragma unroll
        for (int ks = 0; ks < 2; ks++) {
            uint32_t ah[4][4], al[4][4], bh[4][2], bl[4][2];
            int am = wm * 64 + (lane & 15);
            int ak = ks * 16 + (lane >> 4) * 8;
#pragma unroll
            for (int mt = 0; mt < 4; mt++) {
                ldm_x4(ah[mt], sptr(&Ah[am + mt * 16][ak]));
                ldm_x4(al[mt], sptr(&Al[am + mt * 16][ak]));
            }
            int bnr = wn * 32 + (lane & 7);
            int bk = ks * 16 + ((lane >> 3) & 1) * 8;
#pragma unroll
            for (int nt = 0; nt < 4; nt++) {
                ldm_x2(bh[nt], sptr(&Bh[bnr + nt * 8][bk]));
                ldm_x2(bl[nt], sptr(&Bl[bnr + nt * 8][bk]));
            }
#pragma unroll
            for (int mt = 0; mt < 4; mt++)
#pragma unroll
                for (int nt = 0; nt < 4; nt++) {
                    mma_bf16(acc[mt][nt], ah[mt], bh[nt]);
                    mma_bf16(acc[mt][nt], ah[mt], bl[nt]);
                    mma_bf16(acc[mt][nt], al[mt], bh[nt]);
                }
        }
        __syncthreads();
    }

    // ---- epilogue ----
    const int g = lane >> 2, tig = lane & 3;
#pragma unroll
    for (int mt = 0; mt < 4; mt++) {
#pragma unroll
        for (int nt = 0; nt < 4; nt++) {
            int row = bm + wm * 64 + mt * 16 + g;
            int col = bn + wn * 32 + nt * 8 + tig * 2;
            float b0 = bias ? bias[col] : 0.f;
            float b1 = bias ? bias[col + 1] : 0.f;
            *(float2*)&C[(size_t)row * ldc + col] =
                make_float2(acc[mt][nt][0] + b0, acc[mt][nt][1] + b1);
            *(float2*)&C[(size_t)(row + 8) * ldc + col] =
                make_float2(acc[mt][nt][2] + b0, acc[mt][nt][3] + b1);
        }
    }
}

// ======================================================================
// Tensor-core GEMM  C = A * B  (attn @ V)
// A[M,K] rm, B[K,N] rm. Tiles 128x64x32, 256 thr (8 warps 4x2, 32x32 each).
// ======================================================================
__global__ void __launch_bounds__(256)
gemm_nn_tc(const float* __restrict__ A, int lda,
           const float* __restrict__ B, int ldb,
           float* __restrict__ C, int ldc,
           int K, int zdiv,
           size_t sA1, size_t sA2,
           size_t sB1, size_t sB2,
           size_t sC1, size_t sC2)
{
    int z = blockIdx.z;
    int z1 = z / zdiv, z2 = z % zdiv;
    A += z1 * sA1 + z2 * sA2;
    B += z1 * sB1 + z2 * sB2;
    C += z1 * sC1 + z2 * sC2;

    __shared__ __nv_bfloat16 Ah[128][40], Al[128][40];
    __shared__ __nv_bfloat16 Vh[32][72], Vl[32][72];

    const int bm = blockIdx.y * 128;
    const int tid = threadIdx.x;
    const int warp = tid >> 5, lane = tid & 31;
    const int wm = warp >> 1, wn = warp & 1;          // 4 x 2 warps

    float acc[2][4][4];
#pragma unroll
    for (int i = 0; i < 2; i++)
#pragma unroll
        for (int j = 0; j < 4; j++)
#pragma unroll
            for (int l = 0; l < 4; l++) acc[i][j][l] = 0.f;

    for (int k0 = 0; k0 < K; k0 += 32) {
        // A tile 128x32
#pragma unroll
        for (int i = 0; i < 4; i++) {
            int f = tid + i * 256;
            int row = f >> 3, c = (f & 7) * 4;
            float4 a = *(const float4*)(A + (size_t)(bm + row) * lda + k0 + c);
            __nv_bfloat16 h0, l0, h1, l1, h2, l2, h3, l3;
            split_bf16(a.x, h0, l0); split_bf16(a.y, h1, l1);
            split_bf16(a.z, h2, l2); split_bf16(a.w, h3, l3);
            Ah[row][c] = h0; Ah[row][c+1] = h1; Ah[row][c+2] = h2; Ah[row][c+3] = h3;
            Al[row][c] = l0; Al[row][c+1] = l1; Al[row][c+2] = l2; Al[row][c+3] = l3;
        }
        // V tile 32x64
#pragma unroll
        for (int i = 0; i < 2; i++) {
            int f = tid + i * 256;
            int kr = f >> 4, c = (f & 15) * 4;
            float4 b = *(const float4*)(B + (size_t)(k0 + kr) * ldb + c);
            __nv_bfloat16 h0, l0, h1, l1, h2, l2, h3, l3;
            split_bf16(b.x, h0, l0); split_bf16(b.y, h1, l1);
            split_bf16(b.z, h2, l2); split_bf16(b.w, h3, l3);
            Vh[kr][c] = h0; Vh[kr][c+1] = h1; Vh[kr][c+2] = h2; Vh[kr][c+3] = h3;
            Vl[kr][c] = l0; Vl[kr][c+1] = l1; Vl[kr][c+2] = l2; Vl[kr][c+3] = l3;
        }
        __syncthreads();

#pragma unroll
        for (int ks = 0; ks < 2; ks++) {
            uint32_t ah[2][4], al[2][4], bh[4][2], bl[4][2];
            int amr = wm * 32 + (lane & 15);
            int ak = ks * 16 + (lane >> 4) * 8;
#pragma unroll
            for (int mt = 0; mt < 2; mt++) {
                ldm_x4(ah[mt], sptr(&Ah[amr + mt * 16][ak]));
                ldm_x4(al[mt], sptr(&Al[amr + mt * 16][ak]));
            }
            int vk = ks * 16 + (lane & 15);
#pragma unroll
            for (int nt = 0; nt < 4; nt++) {
                int vn = wn * 32 + nt * 8;
                ldm_x2t(bh[nt], sptr(&Vh[vk][vn]));
                ldm_x2t(bl[nt], sptr(&Vl[vk][vn]));
            }
#pragma unroll
            for (int mt = 0; mt < 2; mt++)
#pragma unroll
                for (int nt = 0; nt < 4; nt++) {
                    mma_bf16(acc[mt][nt], ah[mt], bh[nt]);
                    mma_bf16(acc[mt][nt], ah[mt], bl[nt]);
                    mma_bf16(acc[mt][nt], al[mt], bh[nt]);
                }
        }
        __syncthreads();
    }

    const int g = lane >> 2, tig = lane & 3;
#pragma unroll
    for (int mt = 0; mt < 2; mt++) {
#pragma unroll
        for (int nt = 0; nt < 4; nt++) {
            int row = bm + wm * 32 + mt * 16 + g;
            int col = wn * 32 + nt * 8 + tig * 2;
            *(float2*)&C[(size_t)row * ldc + col] =
                make_float2(acc[mt][nt][0], acc[mt][nt][1]);
            *(float2*)&C[(size_t)(row + 8) * ldc + col] =
                make_float2(acc[mt][nt][2], acc[mt][nt][3]);
        }
    }
}

// ======================================================================
// Row softmax in-place. One block (256 thr) per row of 2048.
// ======================================================================
__device__ __forceinline__ float warp_max(float v) {
#pragma unroll
    for (int o = 16; o; o >>= 1) v = fmaxf(v, __shfl_xor_sync(0xffffffffu, v, o));
    return v;
}
__device__ __forceinline__ float warp_sum(float v) {
#pragma unroll
    for (int o = 16; o; o >>= 1) v += __shfl_xor_sync(0xffffffffu, v, o);
    return v;
}

__global__ void __launch_bounds__(256)
softmax_rows(float* __restrict__ scores)
{
    size_t row = blockIdx.x;
    float* p = scores + row * (size_t)S_;
    const int t = threadIdx.x;

    float v[8];
    float mx = -INFINITY;
#pragma unroll
    for (int i = 0; i < 8; i++) {
        v[i] = p[t + i * 256];
        mx = fmaxf(mx, v[i]);
    }

    __shared__ float red[8];
    float wm = warp_max(mx);
    if ((t & 31) == 0) red[t >> 5] = wm;
    __syncthreads();
    if (t < 32) {
        float x = (t < 8) ? red[t] : -INFINITY;
        x = warp_max(x);
        if (t == 0) red[0] = x;
    }
    __syncthreads();
    mx = red[0];

    float s = 0.f;
#pragma unroll
    for (int i = 0; i < 8; i++) {
        v[i] = __expf(v[i] - mx);
        s += v[i];
    }
    __syncthreads();
    float ws = warp_sum(s);
    if ((t & 31) == 0) red[t >> 5] = ws;
    __syncthreads();
    if (t < 32) {
        float x = (t < 8) ? red[t] : 0.f;
        x = warp_sum(x);
        if (t == 0) red[0] = x;
    }
    __syncthreads();
    float inv = 1.0f / red[0];

#pragma unroll
    for (int i = 0; i < 8; i++) p[t + i * 256] = v[i] * inv;
}

// ======================================================================
// avg_attn[b,q,k] = mean_h attn[b,h,q,k]
// ======================================================================
__global__ void __launch_bounds__(256)
avg_heads(const float* __restrict__ scores, float* __restrict__ out)
{
    size_t idx = (size_t)blockIdx.x * 256 + threadIdx.x;   // < B*S*S
    size_t b = idx / ((size_t)S_ * S_);
    size_t rem = idx % ((size_t)S_ * S_);
    float s = 0.f;
#pragma unroll
    for (int h = 0; h < H_; h++)
        s += scores[((b * H_ + h) * (size_t)S_ * S_) + rem];
    out[idx] = s * (1.0f / H_);
}

// ======================================================================
extern "C" void kernel_launch(void* const* d_in, const int* in_sizes, int n_in,
                              void* d_out, int out_size)
{
    const float* query = (const float*)d_in[0];
    const float* Wq = (const float*)d_in[1];
    const float* bq = (const float*)d_in[2];
    const float* Wk = (const float*)d_in[3];
    const float* bk = (const float*)d_in[4];
    const float* Wv = (const float*)d_in[5];
    const float* bv = (const float*)d_in[6];
    const float* Wo = (const float*)d_in[7];
    const float* bo = (const float*)d_in[8];
    float* out = (float*)d_out;

    float *Q, *K, *V, *CTX, *SC;
    cudaGetSymbolAddress((void**)&Q,   g_Q);
    cudaGetSymbolAddress((void**)&K,   g_K);
    cudaGetSymbolAddress((void**)&V,   g_V);
    cudaGetSymbolAddress((void**)&CTX, g_ctx);
    cudaGetSymbolAddress((void**)&SC,  g_scores);

    const int M = B_ * S_;   // 4096
    const float iscale = 1.0f / 8.0f;   // 1/sqrt(HD)

    // ---- Q/K/V projections: [4096,1024] @ W^T + b ----
    dim3 gproj(D_ / 128, M / 128, 1);
    gemm_nt_tc<<<gproj, 256>>>(query, D_, Wq, D_, Q, D_, D_, 1.f, bq,
                               1, 0, 0, 0, 0, 0, 0);
    gemm_nt_tc<<<gproj, 256>>>(query, D_, Wk, D_, K, D_, D_, 1.f, bk,
                               1, 0, 0, 0, 0, 0, 0);
    gemm_nt_tc<<<gproj, 256>>>(query, D_, Wv, D_, V, D_, D_, 1.f, bv,
                               1, 0, 0, 0, 0, 0, 0);

    // ---- scores[b,h] = (Q_h * 1/8) @ K_h^T : batched over z = b*H+h ----
    dim3 gsc(S_ / 128, S_ / 128, B_ * H_);
    gemm_nt_tc<<<gsc, 256>>>(Q, D_, K, D_, SC, S_, HD_, iscale, nullptr,
                             H_,
                             (size_t)S_ * D_, HD_,
                             (size_t)S_ * D_, HD_,
                             (size_t)H_ * S_ * S_, (size_t)S_ * S_);

    // ---- softmax over each of B*H*S rows ----
    softmax_rows<<<B_ * H_ * S_, 256>>>(SC);

    // ---- avg over heads -> second output chunk ----
    avg_heads<<<(B_ * (size_t)S_ * S_) / 256, 256>>>(SC, out + (size_t)M * D_);

    // ---- ctx[b,h] = attn @ V_h : batched ----
    dim3 gcx(1, S_ / 128, B_ * H_);
    gemm_nn_tc<<<gcx, 256>>>(SC, S_, V, D_, CTX, D_, S_,
                             H_,
                             (size_t)H_ * S_ * S_, (size_t)S_ * S_,
                             (size_t)S_ * D_, HD_,
                             (size_t)S_ * D_, HD_);

    // ---- output projection ----
    gemm_nt_tc<<<gproj, 256>>>(CTX, D_, Wo, D_, out, D_, D_, 1.f, bo,
                               1, 0, 0, 0, 0, 0, 0);
}

// round 4
// speedup vs baseline: 3.6305x; 1.0304x over previous
#include <cuda_runtime.h>
#include <cuda_bf16.h>
#include <math.h>
#include <stdint.h>

#define B_  2
#define S_  2048
#define D_  1024
#define H_  16
#define HD_ 64

typedef __nv_bfloat16 bf16;

// ---------------- scratch (no cudaMalloc allowed) ----------------
__device__ bf16  g_xh[(size_t)B_ * S_ * D_],  g_xl[(size_t)B_ * S_ * D_];     // split query
__device__ bf16  g_Wh[(size_t)4 * D_ * D_],   g_Wl[(size_t)4 * D_ * D_];      // split weights
__device__ bf16  g_Qh[(size_t)B_ * S_ * D_],  g_Ql[(size_t)B_ * S_ * D_];
__device__ bf16  g_Kh[(size_t)B_ * S_ * D_],  g_Kl[(size_t)B_ * S_ * D_];
__device__ bf16  g_Vh[(size_t)B_ * S_ * D_],  g_Vl[(size_t)B_ * S_ * D_];
__device__ bf16  g_ch[(size_t)B_ * S_ * D_],  g_cl[(size_t)B_ * S_ * D_];     // split ctx
__device__ bf16  g_Ph[(size_t)B_ * H_ * S_ * S_], g_Pl[(size_t)B_ * H_ * S_ * S_]; // attn
__device__ float g_scores[(size_t)B_ * H_ * S_ * S_];                          // 536 MB

// ======================= PTX helpers =======================
__device__ __forceinline__ uint32_t sptr(const void* p) {
    return (uint32_t)__cvta_generic_to_shared(p);
}
__device__ __forceinline__ void cpa16(uint32_t dst, const void* src) {
    asm volatile("cp.async.cg.shared.global [%0], [%1], 16;" :: "r"(dst), "l"(src));
}
__device__ __forceinline__ void cpa_commit() {
    asm volatile("cp.async.commit_group;");
}
template<int N> __device__ __forceinline__ void cpa_wait() {
    asm volatile("cp.async.wait_group %0;" :: "n"(N));
}
__device__ __forceinline__ void ldm_x4(uint32_t (&r)[4], uint32_t addr) {
    asm volatile("ldmatrix.sync.aligned.m8n8.x4.shared.b16 {%0,%1,%2,%3}, [%4];"
                 : "=r"(r[0]), "=r"(r[1]), "=r"(r[2]), "=r"(r[3]) : "r"(addr));
}
__device__ __forceinline__ void ldm_x2(uint32_t (&r)[2], uint32_t addr) {
    asm volatile("ldmatrix.sync.aligned.m8n8.x2.shared.b16 {%0,%1}, [%2];"
                 : "=r"(r[0]), "=r"(r[1]) : "r"(addr));
}
__device__ __forceinline__ void ldm_x2t(uint32_t (&r)[2], uint32_t addr) {
    asm volatile("ldmatrix.sync.aligned.m8n8.x2.trans.shared.b16 {%0,%1}, [%2];"
                 : "=r"(r[0]), "=r"(r[1]) : "r"(addr));
}
__device__ __forceinline__ void mma_bf16(float (&c)[4], const uint32_t (&a)[4],
                                         const uint32_t (&b)[2]) {
    asm volatile(
        "mma.sync.aligned.m16n8k16.row.col.f32.bf16.bf16.f32 "
        "{%0,%1,%2,%3}, {%4,%5,%6,%7}, {%8,%9}, {%0,%1,%2,%3};"
        : "+f"(c[0]), "+f"(c[1]), "+f"(c[2]), "+f"(c[3])
        : "r"(a[0]), "r"(a[1]), "r"(a[2]), "r"(a[3]), "r"(b[0]), "r"(b[1]));
}
__device__ __forceinline__ void split_bf16(float x, bf16& hi, bf16& lo) {
    hi = __float2bfloat16(x);
    lo = __float2bfloat16(x - __bfloat162float(hi));
}

// ======================================================================
// split kernels
// ======================================================================
__global__ void __launch_bounds__(256)
split_query(const float* __restrict__ x, bf16* __restrict__ xh, bf16* __restrict__ xl)
{
    size_t i = (size_t)blockIdx.x * 256 + threadIdx.x;
    split_bf16(x[i], xh[i], xl[i]);
}

__global__ void __launch_bounds__(256)
split_weights(const float* __restrict__ Wq, const float* __restrict__ Wk,
              const float* __restrict__ Wv, const float* __restrict__ Wo,
              bf16* __restrict__ Wh, bf16* __restrict__ Wl)
{
    size_t i = (size_t)blockIdx.x * 256 + threadIdx.x;   // < D*D
    const size_t n = (size_t)D_ * D_;
    split_bf16(Wq[i], Wh[i],         Wl[i]);
    split_bf16(Wk[i], Wh[i + n],     Wl[i + n]);
    split_bf16(Wv[i], Wh[i + 2*n],   Wl[i + 2*n]);
    split_bf16(Wo[i], Wh[i + 3*n],   Wl[i + 3*n]);
}

// ======================================================================
// bf16x3 tensor-core GEMM  C = alpha * A * B^T (+bias)
// A[M,K] = (Agh, Agl), B[N,K] = (Bgh, Bgl) bf16 row-major.
// Output: fp32 Cf OR bf16 split (Coh, Col).
// Tiles 128x128x16, double-buffered cp.async. 256 thr, 8 warps (2x4), 64x32.
// ======================================================================
__global__ void __launch_bounds__(256)
gemm_nt_tc(const bf16* __restrict__ Agh, const bf16* __restrict__ Agl, int lda,
           const bf16* __restrict__ Bgh, const bf16* __restrict__ Bgl, int ldb,
           float* __restrict__ Cf, bf16* __restrict__ Coh, bf16* __restrict__ Col,
           int ldc, int K, float alpha, const float* __restrict__ bias,
           int zdiv,
           size_t sA1, size_t sA2, size_t sB1, size_t sB2, size_t sC1, size_t sC2)
{
    int z = blockIdx.z;
    int z1 = z / zdiv, z2 = z % zdiv;
    Agh += z1 * sA1 + z2 * sA2;  Agl += z1 * sA1 + z2 * sA2;
    Bgh += z1 * sB1 + z2 * sB2;  Bgl += z1 * sB1 + z2 * sB2;
    size_t coff = z1 * sC1 + z2 * sC2;

    __shared__ bf16 sA[2][2][128][24];   // [stage][hi/lo][row][k]  (24 pitch: 48B rows)
    __shared__ bf16 sB[2][2][128][24];

    const int bm = blockIdx.y * 128;
    const int bn = blockIdx.x * 128;
    const int tid = threadIdx.x;
    const int warp = tid >> 5, lane = tid & 31;
    const int wm = warp >> 2, wn = warp & 3;

    const int lrow = tid >> 1;          // 0..127
    const int lhalf = tid & 1;          // 16B half of 16 cols

    float acc[4][4][4];
#pragma unroll
    for (int i = 0; i < 4; i++)
#pragma unroll
        for (int j = 0; j < 4; j++)
#pragma unroll
            for (int l = 0; l < 4; l++) acc[i][j][l] = 0.f;

    const int KT = K >> 4;

    auto issue = [&](int kt, int st) {
        int k0 = kt * 16 + lhalf * 8;
        cpa16(sptr(&sA[st][0][lrow][lhalf * 8]), Agh + (size_t)(bm + lrow) * lda + k0);
        cpa16(sptr(&sA[st][1][lrow][lhalf * 8]), Agl + (size_t)(bm + lrow) * lda + k0);
        cpa16(sptr(&sB[st][0][lrow][lhalf * 8]), Bgh + (size_t)(bn + lrow) * ldb + k0);
        cpa16(sptr(&sB[st][1][lrow][lhalf * 8]), Bgl + (size_t)(bn + lrow) * ldb + k0);
        cpa_commit();
    };

    issue(0, 0);

    for (int kt = 0; kt < KT; kt++) {
        int st = kt & 1;
        if (kt + 1 < KT) { issue(kt + 1, st ^ 1); cpa_wait<1>(); }
        else             { cpa_wait<0>(); }
        __syncthreads();

        uint32_t ah[4][4], al[4][4], bh[4][2], bl[4][2];
        int am = wm * 64 + (lane & 15);
        int ak = (lane >> 4) * 8;
#pragma unroll
        for (int mt = 0; mt < 4; mt++) {
            ldm_x4(ah[mt], sptr(&sA[st][0][am + mt * 16][ak]));
            ldm_x4(al[mt], sptr(&sA[st][1][am + mt * 16][ak]));
        }
        int bnr = wn * 32 + (lane & 7);
        int bk = ((lane >> 3) & 1) * 8;
#pragma unroll
        for (int nt = 0; nt < 4; nt++) {
            ldm_x2(bh[nt], sptr(&sB[st][0][bnr + nt * 8][bk]));
            ldm_x2(bl[nt], sptr(&sB[st][1][bnr + nt * 8][bk]));
        }
#pragma unroll
        for (int mt = 0; mt < 4; mt++)
#pragma unroll
            for (int nt = 0; nt < 4; nt++) {
                mma_bf16(acc[mt][nt], ah[mt], bh[nt]);
                mma_bf16(acc[mt][nt], ah[mt], bl[nt]);
                mma_bf16(acc[mt][nt], al[mt], bh[nt]);
            }
        __syncthreads();
    }

    // ---- epilogue ----
    const int g = lane >> 2, tig = lane & 3;
#pragma unroll
    for (int mt = 0; mt < 4; mt++) {
#pragma unroll
        for (int nt = 0; nt < 4; nt++) {
            int row = bm + wm * 64 + mt * 16 + g;
            int col = bn + wn * 32 + nt * 8 + tig * 2;
            float b0 = bias ? bias[col] : 0.f;
            float b1 = bias ? bias[col + 1] : 0.f;
            float v00 = alpha * acc[mt][nt][0] + b0;
            float v01 = alpha * acc[mt][nt][1] + b1;
            float v10 = alpha * acc[mt][nt][2] + b0;
            float v11 = alpha * acc[mt][nt][3] + b1;
            size_t o0 = coff + (size_t)row * ldc + col;
            size_t o1 = coff + (size_t)(row + 8) * ldc + col;
            if (Cf) {
                *(float2*)&Cf[o0] = make_float2(v00, v01);
                *(float2*)&Cf[o1] = make_float2(v10, v11);
            } else {
                bf16 h0, l0, h1, l1;
                split_bf16(v00, h0, l0); split_bf16(v01, h1, l1);
                *(__nv_bfloat162*)&Coh[o0] = __nv_bfloat162(h0, h1);
                *(__nv_bfloat162*)&Col[o0] = __nv_bfloat162(l0, l1);
                split_bf16(v10, h0, l0); split_bf16(v11, h1, l1);
                *(__nv_bfloat162*)&Coh[o1] = __nv_bfloat162(h0, h1);
                *(__nv_bfloat162*)&Col[o1] = __nv_bfloat162(l0, l1);
            }
        }
    }
}

// ======================================================================
// bf16x3 tensor-core GEMM  C = A * B  (attn @ V), split bf16 output.
// A[M,K] = (Agh,Agl) rm, B[K,N] = (Bgh,Bgl) rm. Tiles 128x64x16,
// double-buffered. 8 warps (4x2), each 32x32.
// ======================================================================
__global__ void __launch_bounds__(256)
gemm_nn_tc(const bf16* __restrict__ Agh, const bf16* __restrict__ Agl, int lda,
           const bf16* __restrict__ Bgh, const bf16* __restrict__ Bgl, int ldb,
           bf16* __restrict__ Coh, bf16* __restrict__ Col, int ldc,
           int K, int zdiv,
           size_t sA1, size_t sA2, size_t sB1, size_t sB2, size_t sC1, size_t sC2)
{
    int z = blockIdx.z;
    int z1 = z / zdiv, z2 = z % zdiv;
    Agh += z1 * sA1 + z2 * sA2;  Agl += z1 * sA1 + z2 * sA2;
    Bgh += z1 * sB1 + z2 * sB2;  Bgl += z1 * sB1 + z2 * sB2;
    size_t coff = z1 * sC1 + z2 * sC2;

    __shared__ bf16 sA[2][2][128][24];
    __shared__ bf16 sV[2][2][16][72];    // 144B rows (16B multiple)

    const int bm = blockIdx.y * 128;
    const int tid = threadIdx.x;
    const int warp = tid >> 5, lane = tid & 31;
    const int wm = warp >> 1, wn = warp & 1;

    float acc[2][4][4];
#pragma unroll
    for (int i = 0; i < 2; i++)
#pragma unroll
        for (int j = 0; j < 4; j++)
#pragma unroll
            for (int l = 0; l < 4; l++) acc[i][j][l] = 0.f;

    const int KT = K >> 4;

    auto issue = [&](int kt, int st) {
        int k0 = kt * 16;
        // A: 2 arrays x 128 rows x 2 halves = 512 chunks, 2/thread
#pragma unroll
        for (int i = 0; i < 2; i++) {
            int id = i * 256 + tid;
            int arr = id >> 8, row = (id & 255) >> 1, half = id & 1;
            const bf16* src = (arr ? Agl : Agh) + (size_t)(bm + row) * lda + k0 + half * 8;
            cpa16(sptr(&sA[st][arr][row][half * 8]), src);
        }
        // V: 2 arrays x 16 rows x 4 chunks(64 cols) = 128... -> 256 chunks total, 1/thread
        {
            int arr = tid >> 7, rr = (tid & 127) >> 3, cc = tid & 7;
            const bf16* src = (arr ? Bgl : Bgh) + (size_t)(k0 + rr) * ldb + cc * 8;
            cpa16(sptr(&sV[st][arr][rr][cc * 8]), src);
        }
        cpa_commit();
    };

    issue(0, 0);

    for (int kt = 0; kt < KT; kt++) {
        int st = kt & 1;
        if (kt + 1 < KT) { issue(kt + 1, st ^ 1); cpa_wait<1>(); }
        else             { cpa_wait<0>(); }
        __syncthreads();

        uint32_t ah[2][4], al[2][4], bh[4][2], bl[4][2];
        int amr = wm * 32 + (lane & 15);
        int ak = (lane >> 4) * 8;
#pragma unroll
        for (int mt = 0; mt < 2; mt++) {
            ldm_x4(ah[mt], sptr(&sA[st][0][amr + mt * 16][ak]));
            ldm_x4(al[mt], sptr(&sA[st][1][amr + mt * 16][ak]));
        }
        int vk = lane & 15;
#pragma unroll
        for (int nt = 0; nt < 4; nt++) {
            int vn = wn * 32 + nt * 8;
            ldm_x2t(bh[nt], sptr(&sV[st][0][vk][vn]));
            ldm_x2t(bl[nt], sptr(&sV[st][1][vk][vn]));
        }
#pragma unroll
        for (int mt = 0; mt < 2; mt++)
#pragma unroll
            for (int nt = 0; nt < 4; nt++) {
                mma_bf16(acc[mt][nt], ah[mt], bh[nt]);
                mma_bf16(acc[mt][nt], ah[mt], bl[nt]);
                mma_bf16(acc[mt][nt], al[mt], bh[nt]);
            }
        __syncthreads();
    }

    const int g = lane >> 2, tig = lane & 3;
#pragma unroll
    for (int mt = 0; mt < 2; mt++) {
#pragma unroll
        for (int nt = 0; nt < 4; nt++) {
            int row = bm + wm * 32 + mt * 16 + g;
            int col = wn * 32 + nt * 8 + tig * 2;
            size_t o0 = coff + (size_t)row * ldc + col;
            size_t o1 = coff + (size_t)(row + 8) * ldc + col;
            bf16 h0, l0, h1, l1;
            split_bf16(acc[mt][nt][0], h0, l0); split_bf16(acc[mt][nt][1], h1, l1);
            *(__nv_bfloat162*)&Coh[o0] = __nv_bfloat162(h0, h1);
            *(__nv_bfloat162*)&Col[o0] = __nv_bfloat162(l0, l1);
            split_bf16(acc[mt][nt][2], h0, l0); split_bf16(acc[mt][nt][3], h1, l1);
            *(__nv_bfloat162*)&Coh[o1] = __nv_bfloat162(h0, h1);
            *(__nv_bfloat162*)&Col[o1] = __nv_bfloat162(l0, l1);
        }
    }
}

// ======================================================================
// Fused softmax (all 16 heads of one (b,q) row) + avg + bf16 hi/lo attn
// ======================================================================
__device__ __forceinline__ float warp_max(float v) {
#pragma unroll
    for (int o = 16; o; o >>= 1) v = fmaxf(v, __shfl_xor_sync(0xffffffffu, v, o));
    return v;
}
__device__ __forceinline__ float warp_sum(float v) {
#pragma unroll
    for (int o = 16; o; o >>= 1) v += __shfl_xor_sync(0xffffffffu, v, o);
    return v;
}
__device__ __forceinline__ float blk_max(float v, float* red, int t) {
    v = warp_max(v);
    if ((t & 31) == 0) red[t >> 5] = v;
    __syncthreads();
    if (t < 32) {
        float x = (t < 8) ? red[t] : -INFINITY;
        x = warp_max(x);
        if (t == 0) red[0] = x;
    }
    __syncthreads();
    float r = red[0];
    __syncthreads();
    return r;
}
__device__ __forceinline__ float blk_sum(float v, float* red, int t) {
    v = warp_sum(v);
    if ((t & 31) == 0) red[t >> 5] = v;
    __syncthreads();
    if (t < 32) {
        float x = (t < 8) ? red[t] : 0.f;
        x = warp_sum(x);
        if (t == 0) red[0] = x;
    }
    __syncthreads();
    float r = red[0];
    __syncthreads();
    return r;
}

__global__ void __launch_bounds__(256)
softmax_avg(const float* __restrict__ SC, bf16* __restrict__ Ph,
            bf16* __restrict__ Pl, float* __restrict__ avg)
{
    const int bq = blockIdx.x;
    const int b = bq >> 11, q = bq & 2047;
    const int t = threadIdx.x;
    __shared__ float red[8];

    float accv[8] = {0, 0, 0, 0, 0, 0, 0, 0};

#pragma unroll 1
    for (int h = 0; h < H_; h++) {
        size_t off = (((size_t)b * H_ + h) * S_ + q) * (size_t)S_;
        float4 v0 = *(const float4*)(SC + off + t * 8);
        float4 v1 = *(const float4*)(SC + off + t * 8 + 4);
        float v[8] = {v0.x, v0.y, v0.z, v0.w, v1.x, v1.y, v1.z, v1.w};

        float mx = v[0];
#pragma unroll
        for (int i = 1; i < 8; i++) mx = fmaxf(mx, v[i]);
        mx = blk_max(mx, red, t);

        float s = 0.f;
#pragma unroll
        for (int i = 0; i < 8; i++) { v[i] = __expf(v[i] - mx); s += v[i]; }
        s = blk_sum(s, red, t);
        float inv = 1.0f / s;

        __nv_bfloat162 hv[4], lv[4];
#pragma unroll
        for (int i = 0; i < 4; i++) {
            float p0 = v[2 * i] * inv, p1 = v[2 * i + 1] * inv;
            accv[2 * i] += p0; accv[2 * i + 1] += p1;
            bf16 h0, l0, h1, l1;
            split_bf16(p0, h0, l0); split_bf16(p1, h1, l1);
            hv[i] = __nv_bfloat162(h0, h1);
            lv[i] = __nv_bfloat162(l0, l1);
        }
        *(uint4*)&Ph[off + t * 8] = *(uint4*)hv;
        *(uint4*)&Pl[off + t * 8] = *(uint4*)lv;
    }

    size_t ao = ((size_t)b * S_ + q) * (size_t)S_ + t * 8;
    float4 a0 = make_float4(accv[0], accv[1], accv[2], accv[3]);
    float4 a1 = make_float4(accv[4], accv[5], accv[6], accv[7]);
    const float ih = 1.0f / H_;
    a0.x *= ih; a0.y *= ih; a0.z *= ih; a0.w *= ih;
    a1.x *= ih; a1.y *= ih; a1.z *= ih; a1.w *= ih;
    *(float4*)(avg + ao) = a0;
    *(float4*)(avg + ao + 4) = a1;
}

// ======================================================================
extern "C" void kernel_launch(void* const* d_in, const int* in_sizes, int n_in,
                              void* d_out, int out_size)
{
    const float* query = (const float*)d_in[0];
    const float* Wq = (const float*)d_in[1];
    const float* bq = (const float*)d_in[2];
    const float* Wk = (const float*)d_in[3];
    const float* bk = (const float*)d_in[4];
    const float* Wv = (const float*)d_in[5];
    const float* bv = (const float*)d_in[6];
    const float* Wo = (const float*)d_in[7];
    const float* bo = (const float*)d_in[8];
    float* out = (float*)d_out;

    bf16 *xh, *xl, *Wh, *Wl, *Qh, *Ql, *Kh, *Kl, *Vh, *Vl, *ch, *cl, *Ph, *Pl;
    float* SC;
    cudaGetSymbolAddress((void**)&xh, g_xh); cudaGetSymbolAddress((void**)&xl, g_xl);
    cudaGetSymbolAddress((void**)&Wh, g_Wh); cudaGetSymbolAddress((void**)&Wl, g_Wl);
    cudaGetSymbolAddress((void**)&Qh, g_Qh); cudaGetSymbolAddress((void**)&Ql, g_Ql);
    cudaGetSymbolAddress((void**)&Kh, g_Kh); cudaGetSymbolAddress((void**)&Kl, g_Kl);
    cudaGetSymbolAddress((void**)&Vh, g_Vh); cudaGetSymbolAddress((void**)&Vl, g_Vl);
    cudaGetSymbolAddress((void**)&ch, g_ch); cudaGetSymbolAddress((void**)&cl, g_cl);
    cudaGetSymbolAddress((void**)&Ph, g_Ph); cudaGetSymbolAddress((void**)&Pl, g_Pl);
    cudaGetSymbolAddress((void**)&SC, g_scores);

    const int M = B_ * S_;                 // 4096
    const size_t DD = (size_t)D_ * D_;
    const float iscale = 1.0f / 8.0f;      // 1/sqrt(HD)

    // ---- operand splits ----
    split_query<<<(B_ * S_ * D_) / 256, 256>>>(query, xh, xl);
    split_weights<<<(D_ * D_) / 256, 256>>>(Wq, Wk, Wv, Wo, Wh, Wl);

    // ---- Q/K/V projections -> bf16 hi/lo ----
    dim3 gproj(D_ / 128, M / 128, 1);
    gemm_nt_tc<<<gproj, 256>>>(xh, xl, D_, Wh, Wl, D_,
                               nullptr, Qh, Ql, D_, D_, 1.f, bq,
                               1, 0, 0, 0, 0, 0, 0);
    gemm_nt_tc<<<gproj, 256>>>(xh, xl, D_, Wh + DD, Wl + DD, D_,
                               nullptr, Kh, Kl, D_, D_, 1.f, bk,
                               1, 0, 0, 0, 0, 0, 0);
    gemm_nt_tc<<<gproj, 256>>>(xh, xl, D_, Wh + 2 * DD, Wl + 2 * DD, D_,
                               nullptr, Vh, Vl, D_, D_, 1.f, bv,
                               1, 0, 0, 0, 0, 0, 0);

    // ---- scores = (Q @ K^T) / 8, fp32, batched z = b*H+h ----
    dim3 gsc(S_ / 128, S_ / 128, B_ * H_);
    gemm_nt_tc<<<gsc, 256>>>(Qh, Ql, D_, Kh, Kl, D_,
                             SC, nullptr, nullptr, S_, HD_, iscale, nullptr,
                             H_,
                             (size_t)S_ * D_, HD_,
                             (size_t)S_ * D_, HD_,
                             (size_t)H_ * S_ * S_, (size_t)S_ * S_);

    // ---- fused softmax + avg + bf16 attn ----
    softmax_avg<<<B_ * S_, 256>>>(SC, Ph, Pl, out + (size_t)M * D_);

    // ---- ctx = attn @ V -> bf16 hi/lo ----
    dim3 gcx(1, S_ / 128, B_ * H_);
    gemm_nn_tc<<<gcx, 256>>>(Ph, Pl, S_, Vh, Vl, D_,
                             ch, cl, D_, S_,
                             H_,
                             (size_t)H_ * S_ * S_, (size_t)S_ * S_,
                             (size_t)S_ * D_, HD_,
                             (size_t)S_ * D_, HD_);

    // ---- output projection -> fp32 out ----
    gemm_nt_tc<<<gproj, 256>>>(ch, cl, D_, Wh + 3 * DD, Wl + 3 * DD, D_,
                               out, nullptr, nullptr, D_, D_, 1.f, bo,
                               1, 0, 0, 0, 0, 0, 0);
}

// round 6
// speedup vs baseline: 4.3243x; 1.1911x over previous
#include <cuda_runtime.h>
#include <cuda_bf16.h>
#include <math.h>
#include <stdint.h>

#define B_  2
#define S_  2048
#define D_  1024
#define H_  16
#define HD_ 64

typedef __nv_bfloat16 bf16;

// ---------------- scratch (no cudaMalloc allowed) ----------------
__device__ bf16  g_xh[(size_t)B_ * S_ * D_],  g_xl[(size_t)B_ * S_ * D_];
__device__ bf16  g_Wh[(size_t)4 * D_ * D_],   g_Wl[(size_t)4 * D_ * D_];
__device__ float g_bias3[3 * D_];
__device__ bf16  g_QKVh[(size_t)B_ * S_ * 3 * D_], g_QKVl[(size_t)B_ * S_ * 3 * D_];
__device__ bf16  g_ch[(size_t)B_ * S_ * D_],  g_cl[(size_t)B_ * S_ * D_];
__device__ bf16  g_Ph[(size_t)B_ * H_ * S_ * S_], g_Pl[(size_t)B_ * H_ * S_ * S_];
__device__ float g_scores[(size_t)B_ * H_ * S_ * S_];   // 536 MB

// ======================= PTX helpers =======================
__device__ __forceinline__ uint32_t sptr(const void* p) {
    return (uint32_t)__cvta_generic_to_shared(p);
}
__device__ __forceinline__ void cpa16(uint32_t dst, const void* src) {
    asm volatile("cp.async.cg.shared.global [%0], [%1], 16;" :: "r"(dst), "l"(src));
}
__device__ __forceinline__ void cpa_commit() {
    asm volatile("cp.async.commit_group;");
}
template<int N> __device__ __forceinline__ void cpa_wait() {
    asm volatile("cp.async.wait_group %0;" :: "n"(N));
}
__device__ __forceinline__ void ldm_x4(uint32_t (&r)[4], uint32_t addr) {
    asm volatile("ldmatrix.sync.aligned.m8n8.x4.shared.b16 {%0,%1,%2,%3}, [%4];"
                 : "=r"(r[0]), "=r"(r[1]), "=r"(r[2]), "=r"(r[3]) : "r"(addr));
}
__device__ __forceinline__ void ldm_x2t(uint32_t (&r)[2], uint32_t addr) {
    asm volatile("ldmatrix.sync.aligned.m8n8.x2.trans.shared.b16 {%0,%1}, [%2];"
                 : "=r"(r[0]), "=r"(r[1]) : "r"(addr));
}
__device__ __forceinline__ void mma_bf16(float (&c)[4], const uint32_t (&a)[4],
                                         uint32_t b0, uint32_t b1) {
    asm volatile(
        "mma.sync.aligned.m16n8k16.row.col.f32.bf16.bf16.f32 "
        "{%0,%1,%2,%3}, {%4,%5,%6,%7}, {%8,%9}, {%0,%1,%2,%3};"
        : "+f"(c[0]), "+f"(c[1]), "+f"(c[2]), "+f"(c[3])
        : "r"(a[0]), "r"(a[1]), "r"(a[2]), "r"(a[3]), "r"(b0), "r"(b1));
}
__device__ __forceinline__ void split_bf16(float x, bf16& hi, bf16& lo) {
    hi = __float2bfloat16(x);
    lo = __float2bfloat16(x - __bfloat162float(hi));
}

// ======================================================================
// split / bias kernels
// ======================================================================
__global__ void __launch_bounds__(256)
split_query(const float* __restrict__ x, bf16* __restrict__ xh, bf16* __restrict__ xl)
{
    size_t i = (size_t)blockIdx.x * 256 + threadIdx.x;
    split_bf16(x[i], xh[i], xl[i]);
}

__global__ void __launch_bounds__(256)
split_weights(const float* __restrict__ Wq, const float* __restrict__ Wk,
              const float* __restrict__ Wv, const float* __restrict__ Wo,
              bf16* __restrict__ Wh, bf16* __restrict__ Wl)
{
    size_t i = (size_t)blockIdx.x * 256 + threadIdx.x;   // < D*D
    const size_t n = (size_t)D_ * D_;
    split_bf16(Wq[i], Wh[i],         Wl[i]);
    split_bf16(Wk[i], Wh[i + n],     Wl[i + n]);
    split_bf16(Wv[i], Wh[i + 2*n],   Wl[i + 2*n]);
    split_bf16(Wo[i], Wh[i + 3*n],   Wl[i + 3*n]);
}

__global__ void __launch_bounds__(256)
concat_bias(const float* __restrict__ a, const float* __restrict__ b,
            const float* __restrict__ c, float* __restrict__ o)
{
    int i = blockIdx.x * 256 + threadIdx.x;   // < D_
    o[i] = a[i]; o[D_ + i] = b[i]; o[2 * D_ + i] = c[i];
}

// ======================================================================
// bf16x3 mma.sync GEMM  C = alpha*A*B^T (+bias), k-chunk 32, 2 stages.
// A[M,K]=(Agh,Agl), B[N,K]=(Bgh,Bgl), bf16 K-major.
// 256 thr, 8 warps (2x4), warp tile 64x32. Dynamic smem 80KB.
// Layout per stage (40960B): AH@0, AL@10240, BH@20480, BL@30720.
// Row pitch 80B (40 bf16): conflict-free ldmatrix, 16B-aligned cp.async.
// ======================================================================
#define NT_STG  40960
#define NT_SMEM (2 * NT_STG)

__global__ void __launch_bounds__(256)
gemm_nt_tc(const bf16* __restrict__ Agh, const bf16* __restrict__ Agl, int lda,
           const bf16* __restrict__ Bgh, const bf16* __restrict__ Bgl, int ldb,
           float* __restrict__ Cf, bf16* __restrict__ Coh, bf16* __restrict__ Col,
           int ldc, int K, float alpha, const float* __restrict__ bias,
           int zdiv,
           size_t sA1, size_t sA2, size_t sB1, size_t sB2, size_t sC1, size_t sC2)
{
    extern __shared__ char dsm[];
    int z = blockIdx.z;
    int z1 = z / zdiv, z2 = z % zdiv;
    Agh += z1 * sA1 + z2 * sA2;  Agl += z1 * sA1 + z2 * sA2;
    Bgh += z1 * sB1 + z2 * sB2;  Bgl += z1 * sB1 + z2 * sB2;
    size_t coff = z1 * sC1 + z2 * sC2;

    const uint32_t sb = sptr(dsm);
    const int bm = blockIdx.y * 128;
    const int bn = blockIdx.x * 128;
    const int tid = threadIdx.x;
    const int warp = tid >> 5, lane = tid & 31;
    const int wm = warp >> 2, wn = warp & 3;

    float acc[4][4][4];
#pragma unroll
    for (int i = 0; i < 4; i++)
#pragma unroll
        for (int j = 0; j < 4; j++)
#pragma unroll
            for (int l = 0; l < 4; l++) acc[i][j][l] = 0.f;

    const int KT = K >> 5;   // 32-k chunks

    // per-thread load map: 2048 x 16B chunks -> 8 per thread
    auto issue = [&](int kt, int st) {
        uint32_t base = sb + st * NT_STG;
        int k0 = kt * 32;
#pragma unroll
        for (int i = 0; i < 8; i++) {
            int ch = i * 256 + tid;               // 0..2047
            int arr = ch >> 9;                    // 0..3 : AH AL BH BL
            int row = (ch & 511) >> 2;            // 0..127
            int c16 = ch & 3;                     // 0..3 (16B units)
            uint32_t dst = base + arr * 10240 + row * 80 + c16 * 16;
            const bf16* src;
            int col = k0 + c16 * 8;
            if (arr == 0)      src = Agh + (size_t)(bm + row) * lda + col;
            else if (arr == 1) src = Agl + (size_t)(bm + row) * lda + col;
            else if (arr == 2) src = Bgh + (size_t)(bn + row) * ldb + col;
            else               src = Bgl + (size_t)(bn + row) * ldb + col;
            cpa16(dst, src);
        }
        cpa_commit();
    };

    issue(0, 0);

    for (int kt = 0; kt < KT; kt++) {
        int st = kt & 1;
        if (kt + 1 < KT) { issue(kt + 1, st ^ 1); cpa_wait<1>(); }
        else             { cpa_wait<0>(); }
        __syncthreads();

        uint32_t base = sb + st * NT_STG;
#pragma unroll
        for (int ks = 0; ks < 2; ks++) {
            // A fragments: x4, lanes 0-15 rows m0-15 k-lo, 16-31 k-hi
            uint32_t ah[4][4], al[4][4];
            {
                int arow = wm * 64 + (lane & 15);
                uint32_t ac = ks * 32 + (lane >> 4) * 16;   // bytes
#pragma unroll
                for (int mt = 0; mt < 4; mt++) {
                    uint32_t ro = (uint32_t)(arow + mt * 16) * 80 + ac;
                    ldm_x4(ah[mt], base + ro);
                    ldm_x4(al[mt], base + 10240 + ro);
                }
            }
            // B fragments: x4 covering nt pair {2p, 2p+1}
            uint32_t bh[2][4], bl[2][4];
            {
                int brow0 = wn * 32 + (lane & 7) + ((lane >> 4) & 1) * 8;
                uint32_t bc = ((lane >> 3) & 1) * 16 + ks * 32;   // bytes
#pragma unroll
                for (int pr = 0; pr < 2; pr++) {
                    uint32_t ro = (uint32_t)(brow0 + pr * 16) * 80 + bc;
                    ldm_x4(bh[pr], base + 20480 + ro);
                    ldm_x4(bl[pr], base + 30720 + ro);
                }
            }
#pragma unroll
            for (int mt = 0; mt < 4; mt++)
#pragma unroll
                for (int nt = 0; nt < 4; nt++) {
                    uint32_t b0h = bh[nt >> 1][(nt & 1) * 2];
                    uint32_t b1h = bh[nt >> 1][(nt & 1) * 2 + 1];
                    uint32_t b0l = bl[nt >> 1][(nt & 1) * 2];
                    uint32_t b1l = bl[nt >> 1][(nt & 1) * 2 + 1];
                    mma_bf16(acc[mt][nt], ah[mt], b0h, b1h);
                    mma_bf16(acc[mt][nt], ah[mt], b0l, b1l);
                    mma_bf16(acc[mt][nt], al[mt], b0h, b1h);
                }
        }
        __syncthreads();
    }

    // ---- epilogue ----
    const int g = lane >> 2, tig = lane & 3;
#pragma unroll
    for (int mt = 0; mt < 4; mt++) {
#pragma unroll
        for (int nt = 0; nt < 4; nt++) {
            int row = bm + wm * 64 + mt * 16 + g;
            int col = bn + wn * 32 + nt * 8 + tig * 2;
            float b0 = bias ? bias[col] : 0.f;
            float b1 = bias ? bias[col + 1] : 0.f;
            float v00 = alpha * acc[mt][nt][0] + b0;
            float v01 = alpha * acc[mt][nt][1] + b1;
            float v10 = alpha * acc[mt][nt][2] + b0;
            float v11 = alpha * acc[mt][nt][3] + b1;
            size_t o0 = coff + (size_t)row * ldc + col;
            size_t o1 = coff + (size_t)(row + 8) * ldc + col;
            if (Cf) {
                *(float2*)&Cf[o0] = make_float2(v00, v01);
                *(float2*)&Cf[o1] = make_float2(v10, v11);
            } else {
                bf16 h0, l0, h1, l1;
                split_bf16(v00, h0, l0); split_bf16(v01, h1, l1);
                *(__nv_bfloat162*)&Coh[o0] = __nv_bfloat162(h0, h1);
                *(__nv_bfloat162*)&Col[o0] = __nv_bfloat162(l0, l1);
                split_bf16(v10, h0, l0); split_bf16(v11, h1, l1);
                *(__nv_bfloat162*)&Coh[o1] = __nv_bfloat162(h0, h1);
                *(__nv_bfloat162*)&Col[o1] = __nv_bfloat162(l0, l1);
            }
        }
    }
}

// ======================================================================
// bf16x3 mma.sync GEMM  C = A * B  (attn @ V), k-chunk 32, 2 stages.
// A[M,K]=(Agh,Agl) rm, B[K,N]=(Bgh,Bgl) rm (N=64 head slice).
// 256 thr, 8 warps (4x2), warp tile 32x32. Dynamic smem 59392B.
// Stage layout: AH@0 (10240), AL@10240, VH@20480 (4608), VL@25088.
// A pitch 80B; V pitch 144B (32 rows x 64 cols).
// ======================================================================
#define NN_STG  29696
#define NN_SMEM (2 * NN_STG)

__global__ void __launch_bounds__(256)
gemm_nn_tc(const bf16* __restrict__ Agh, const bf16* __restrict__ Agl, int lda,
           const bf16* __restrict__ Bgh, const bf16* __restrict__ Bgl, int ldb,
           bf16* __restrict__ Coh, bf16* __restrict__ Col, int ldc,
           int K, int zdiv,
           size_t sA1, size_t sA2, size_t sB1, size_t sB2, size_t sC1, size_t sC2)
{
    extern __shared__ char dsm[];
    int z = blockIdx.z;
    int z1 = z / zdiv, z2 = z % zdiv;
    Agh += z1 * sA1 + z2 * sA2;  Agl += z1 * sA1 + z2 * sA2;
    Bgh += z1 * sB1 + z2 * sB2;  Bgl += z1 * sB1 + z2 * sB2;
    size_t coff = z1 * sC1 + z2 * sC2;

    const uint32_t sb = sptr(dsm);
    const int bm = blockIdx.y * 128;
    const int tid = threadIdx.x;
    const int warp = tid >> 5, lane = tid & 31;
    const int wm = warp >> 1, wn = warp & 1;

    float acc[2][4][4];
#pragma unroll
    for (int i = 0; i < 2; i++)
#pragma unroll
        for (int j = 0; j < 4; j++)
#pragma unroll
            for (int l = 0; l < 4; l++) acc[i][j][l] = 0.f;

    const int KT = K >> 5;

    auto issue = [&](int kt, int st) {
        uint32_t base = sb + st * NN_STG;
        int k0 = kt * 32;
        // A: 1024 chunks (2 arrays x 128 rows x 4), 4/thread
#pragma unroll
        for (int i = 0; i < 4; i++) {
            int ch = i * 256 + tid;
            int arr = ch >> 9, row = (ch & 511) >> 2, c16 = ch & 3;
            const bf16* src = (arr ? Agl : Agh) + (size_t)(bm + row) * lda + k0 + c16 * 8;
            cpa16(base + arr * 10240 + row * 80 + c16 * 16, src);
        }
        // V: 512 chunks (2 arrays x 32 rows x 8), 2/thread
#pragma unroll
        for (int i = 0; i < 2; i++) {
            int ch = i * 256 + tid;
            int arr = ch >> 8, row = (ch & 255) >> 3, c16 = ch & 7;
            const bf16* src = (arr ? Bgl : Bgh) + (size_t)(k0 + row) * ldb + c16 * 8;
            cpa16(base + 20480 + arr * 4608 + row * 144 + c16 * 16, src);
        }
        cpa_commit();
    };

    issue(0, 0);

    for (int kt = 0; kt < KT; kt++) {
        int st = kt & 1;
        if (kt + 1 < KT) { issue(kt + 1, st ^ 1); cpa_wait<1>(); }
        else             { cpa_wait<0>(); }
        __syncthreads();

        uint32_t base = sb + st * NN_STG;
#pragma unroll
        for (int ks = 0; ks < 2; ks++) {
            uint32_t ah[2][4], al[2][4];
            {
                int arow = wm * 32 + (lane & 15);
                uint32_t ac = ks * 32 + (lane >> 4) * 16;
#pragma unroll
                for (int mt = 0; mt < 2; mt++) {
                    uint32_t ro = (uint32_t)(arow + mt * 16) * 80 + ac;
                    ldm_x4(ah[mt], base + ro);
                    ldm_x4(al[mt], base + 10240 + ro);
                }
            }
            uint32_t bh[4][2], bl[4][2];
            {
                int vk = ks * 16 + (lane & 15);
#pragma unroll
                for (int nt = 0; nt < 4; nt++) {
                    uint32_t vo = (uint32_t)vk * 144 + (wn * 32 + nt * 8) * 2;
                    ldm_x2t(bh[nt], base + 20480 + vo);
                    ldm_x2t(bl[nt], base + 25088 + vo);
                }
            }
#pragma unroll
            for (int mt = 0; mt < 2; mt++)
#pragma unroll
                for (int nt = 0; nt < 4; nt++) {
                    mma_bf16(acc[mt][nt], ah[mt], bh[nt][0], bh[nt][1]);
                    mma_bf16(acc[mt][nt], ah[mt], bl[nt][0], bl[nt][1]);
                    mma_bf16(acc[mt][nt], al[mt], bh[nt][0], bh[nt][1]);
                }
        }
        __syncthreads();
    }

    const int g = lane >> 2, tig = lane & 3;
#pragma unroll
    for (int mt = 0; mt < 2; mt++) {
#pragma unroll
        for (int nt = 0; nt < 4; nt++) {
            int row = bm + wm * 32 + mt * 16 + g;
            int col = wn * 32 + nt * 8 + tig * 2;
            size_t o0 = coff + (size_t)row * ldc + col;
            size_t o1 = coff + (size_t)(row + 8) * ldc + col;
            bf16 h0, l0, h1, l1;
            split_bf16(acc[mt][nt][0], h0, l0); split_bf16(acc[mt][nt][1], h1, l1);
            *(__nv_bfloat162*)&Coh[o0] = __nv_bfloat162(h0, h1);
            *(__nv_bfloat162*)&Col[o0] = __nv_bfloat162(l0, l1);
            split_bf16(acc[mt][nt][2], h0, l0); split_bf16(acc[mt][nt][3], h1, l1);
            *(__nv_bfloat162*)&Coh[o1] = __nv_bfloat162(h0, h1);
            *(__nv_bfloat162*)&Col[o1] = __nv_bfloat162(l0, l1);
        }
    }
}

// ======================================================================
// Fused softmax (16 heads per (b,q)) + avg + bf16 hi/lo attn
// ======================================================================
__device__ __forceinline__ float warp_max(float v) {
#pragma unroll
    for (int o = 16; o; o >>= 1) v = fmaxf(v, __shfl_xor_sync(0xffffffffu, v, o));
    return v;
}
__device__ __forceinline__ float warp_sum(float v) {
#pragma unroll
    for (int o = 16; o; o >>= 1) v += __shfl_xor_sync(0xffffffffu, v, o);
    return v;
}
__device__ __forceinline__ float blk_max(float v, float* red, int t) {
    v = warp_max(v);
    if ((t & 31) == 0) red[t >> 5] = v;
    __syncthreads();
    if (t < 32) {
        float x = (t < 8) ? red[t] : -INFINITY;
        x = warp_max(x);
        if (t == 0) red[0] = x;
    }
    __syncthreads();
    float r = red[0];
    __syncthreads();
    return r;
}
__device__ __forceinline__ float blk_sum(float v, float* red, int t) {
    v = warp_sum(v);
    if ((t & 31) == 0) red[t >> 5] = v;
    __syncthreads();
    if (t < 32) {
        float x = (t < 8) ? red[t] : 0.f;
        x = warp_sum(x);
        if (t == 0) red[0] = x;
    }
    __syncthreads();
    float r = red[0];
    __syncthreads();
    return r;
}

__global__ void __launch_bounds__(256)
softmax_avg(const float* __restrict__ SC, bf16* __restrict__ Ph,
            bf16* __restrict__ Pl, float* __restrict__ avg)
{
    const int bq = blockIdx.x;
    const int b = bq >> 11, q = bq & 2047;
    const int t = threadIdx.x;
    __shared__ float red[8];

    float accv[8] = {0, 0, 0, 0, 0, 0, 0, 0};

#pragma unroll 1
    for (int h = 0; h < H_; h++) {
        size_t off = (((size_t)b * H_ + h) * S_ + q) * (size_t)S_;
        float4 v0 = *(const float4*)(SC + off + t * 8);
        float4 v1 = *(const float4*)(SC + off + t * 8 + 4);
        float v[8] = {v0.x, v0.y, v0.z, v0.w, v1.x, v1.y, v1.z, v1.w};

        float mx = v[0];
#pragma unroll
        for (int i = 1; i < 8; i++) mx = fmaxf(mx, v[i]);
        mx = blk_max(mx, red, t);

        float s = 0.f;
#pragma unroll
        for (int i = 0; i < 8; i++) { v[i] = __expf(v[i] - mx); s += v[i]; }
        s = blk_sum(s, red, t);
        float inv = 1.0f / s;

        __nv_bfloat162 hv[4], lv[4];
#pragma unroll
        for (int i = 0; i < 4; i++) {
            float p0 = v[2 * i] * inv, p1 = v[2 * i + 1] * inv;
            accv[2 * i] += p0; accv[2 * i + 1] += p1;
            bf16 h0, l0, h1, l1;
            split_bf16(p0, h0, l0); split_bf16(p1, h1, l1);
            hv[i] = __nv_bfloat162(h0, h1);
            lv[i] = __nv_bfloat162(l0, l1);
        }
        *(uint4*)&Ph[off + t * 8] = *(uint4*)hv;
        *(uint4*)&Pl[off + t * 8] = *(uint4*)lv;
    }

    size_t ao = ((size_t)b * S_ + q) * (size_t)S_ + t * 8;
    const float ih = 1.0f / H_;
    float4 a0 = make_float4(accv[0] * ih, accv[1] * ih, accv[2] * ih, accv[3] * ih);
    float4 a1 = make_float4(accv[4] * ih, accv[5] * ih, accv[6] * ih, accv[7] * ih);
    *(float4*)(avg + ao) = a0;
    *(float4*)(avg + ao + 4) = a1;
}

// ======================================================================
extern "C" void kernel_launch(void* const* d_in, const int* in_sizes, int n_in,
                              void* d_out, int out_size)
{
    const float* query = (const float*)d_in[0];
    const float* Wq = (const float*)d_in[1];
    const float* bq = (const float*)d_in[2];
    const float* Wk = (const float*)d_in[3];
    const float* bk = (const float*)d_in[4];
    const float* Wv = (const float*)d_in[5];
    const float* bv = (const float*)d_in[6];
    const float* Wo = (const float*)d_in[7];
    const float* bo = (const float*)d_in[8];
    float* out = (float*)d_out;

    bf16 *xh, *xl, *Wh, *Wl, *QKVh, *QKVl, *ch, *cl, *Ph, *Pl;
    float *SC, *bias3;
    cudaGetSymbolAddress((void**)&xh, g_xh);   cudaGetSymbolAddress((void**)&xl, g_xl);
    cudaGetSymbolAddress((void**)&Wh, g_Wh);   cudaGetSymbolAddress((void**)&Wl, g_Wl);
    cudaGetSymbolAddress((void**)&QKVh, g_QKVh); cudaGetSymbolAddress((void**)&QKVl, g_QKVl);
    cudaGetSymbolAddress((void**)&ch, g_ch);   cudaGetSymbolAddress((void**)&cl, g_cl);
    cudaGetSymbolAddress((void**)&Ph, g_Ph);   cudaGetSymbolAddress((void**)&Pl, g_Pl);
    cudaGetSymbolAddress((void**)&SC, g_scores);
    cudaGetSymbolAddress((void**)&bias3, g_bias3);

    cudaFuncSetAttribute(gemm_nt_tc, cudaFuncAttributeMaxDynamicSharedMemorySize, NT_SMEM);
    cudaFuncSetAttribute(gemm_nn_tc, cudaFuncAttributeMaxDynamicSharedMemorySize, NN_SMEM);

    const int M = B_ * S_;                 // 4096
    const size_t DD = (size_t)D_ * D_;
    const int N3 = 3 * D_;                 // 3072

    // ---- operand splits + bias concat ----
    split_query<<<(B_ * S_ * D_) / 256, 256>>>(query, xh, xl);
    split_weights<<<(D_ * D_) / 256, 256>>>(Wq, Wk, Wv, Wo, Wh, Wl);
    concat_bias<<<D_ / 256, 256>>>(bq, bk, bv, bias3);

    // ---- merged QKV projection: [4096,1024] @ Wcat^T + bcat -> bf16 hi/lo ----
    gemm_nt_tc<<<dim3(N3 / 128, M / 128, 1), 256, NT_SMEM>>>(
        xh, xl, D_, Wh, Wl, D_,
        nullptr, QKVh, QKVl, N3, D_, 1.f, bias3,
        1, 0, 0, 0, 0, 0, 0);

    // ---- scores = (Q @ K^T)/8, fp32, batched z = b*H+h ----
    gemm_nt_tc<<<dim3(S_ / 128, S_ / 128, B_ * H_), 256, NT_SMEM>>>(
        QKVh, QKVl, N3, QKVh + D_, QKVl + D_, N3,
        SC, nullptr, nullptr, S_, HD_, 0.125f, nullptr,
        H_,
        (size_t)S_ * N3, HD_,
        (size_t)S_ * N3, HD_,
        (size_t)H_ * S_ * S_, (size_t)S_ * S_);

    // ---- fused softmax + avg + bf16 attn ----
    softmax_avg<<<B_ * S_, 256>>>(SC, Ph, Pl, out + (size_t)M * D_);

    // ---- ctx = attn @ V -> bf16 hi/lo ----
    gemm_nn_tc<<<dim3(1, S_ / 128, B_ * H_), 256, NN_SMEM>>>(
        Ph, Pl, S_, QKVh + 2 * D_, QKVl + 2 * D_, N3,
        ch, cl, D_, S_,
        H_,
        (size_t)H_ * S_ * S_, (size_t)S_ * S_,
        (size_t)S_ * N3, HD_,
        (size_t)S_ * D_, HD_);

    // ---- output projection -> fp32 out ----
    gemm_nt_tc<<<dim3(D_ / 128, M / 128, 1), 256, NT_SMEM>>>(
        ch, cl, D_, Wh + 3 * DD, Wl + 3 * DD, D_,
        out, nullptr, nullptr, D_, D_, 1.f, bo,
        1, 0, 0, 0, 0, 0, 0);
}